// round 2
// baseline (speedup 1.0000x reference)
#include <cuda_runtime.h>
#include <cuda_bf16.h>
#include <cstdint>

// Problem constants: x [4, 4096, 2048] fp32, R=64.
#define N_TOK   16384
#define D_DIM   2048
#define R_DIM   64
#define TOK_TILE 128
#define DC      64          // D-chunk per iteration
#define NCHUNK  (D_DIM / DC)
#define EPS     1e-5f

__device__ float g_C1[R_DIM];   // sum_d gamma[d] * w_down[r][d]
__device__ float g_C2[R_DIM];   // sum_d beta[d]  * w_down[r][d]

// ---------------- helpers ----------------

__device__ __forceinline__ float to_tf32(float x) {
    unsigned u;
    asm("cvt.rna.tf32.f32 %0, %1;" : "=r"(u) : "f"(x));
    return __uint_as_float(u);
}

// XOR swizzle, float4 granularity: phys float4 index for (row, c4)
__device__ __forceinline__ int swz4(int row, int c4) {
    return row * 16 + ((c4 + row) & 15);
}
// phys float index for element (row, col), col in [0,64)
__device__ __forceinline__ int swzf(int row, int col) {
    return (row << 6) + ((((col >> 2) + row) & 15) << 2) + (col & 3);
}

__device__ __forceinline__ void mma_tf32(float* c, const unsigned* a, const unsigned* b) {
    asm volatile(
        "mma.sync.aligned.m16n8k8.row.col.f32.tf32.tf32.f32 "
        "{%0,%1,%2,%3}, {%4,%5,%6,%7}, {%8,%9}, {%0,%1,%2,%3};"
        : "+f"(c[0]), "+f"(c[1]), "+f"(c[2]), "+f"(c[3])
        : "r"(a[0]), "r"(a[1]), "r"(a[2]), "r"(a[3]), "r"(b[0]), "r"(b[1]));
}

// ---------------- prep kernel: C1, C2 ----------------

__global__ void prep_c12(const float* __restrict__ w_down,
                         const float* __restrict__ gamma,
                         const float* __restrict__ beta) {
    __shared__ float red1[8], red2[8];
    int r = blockIdx.x;
    float s1 = 0.f, s2 = 0.f;
    for (int d = threadIdx.x; d < D_DIM; d += 256) {
        float w = w_down[r * D_DIM + d];
        s1 += gamma[d] * w;
        s2 += beta[d] * w;
    }
    #pragma unroll
    for (int o = 16; o; o >>= 1) {
        s1 += __shfl_down_sync(0xFFFFFFFFu, s1, o);
        s2 += __shfl_down_sync(0xFFFFFFFFu, s2, o);
    }
    if ((threadIdx.x & 31) == 0) { red1[threadIdx.x >> 5] = s1; red2[threadIdx.x >> 5] = s2; }
    __syncthreads();
    if (threadIdx.x == 0) {
        float t1 = 0.f, t2 = 0.f;
        #pragma unroll
        for (int i = 0; i < 8; i++) { t1 += red1[i]; t2 += red2[i]; }
        g_C1[r] = t1;
        g_C2[r] = t2;
    }
}

// ---------------- main fused kernel ----------------

__global__ __launch_bounds__(256) void adapter_main(
    const float* __restrict__ x,
    const float* __restrict__ gamma,
    const float* __restrict__ w_down,
    const float* __restrict__ b_down,
    const float* __restrict__ w_up,
    const float* __restrict__ b_up,
    const float* __restrict__ scale,
    float* __restrict__ out)
{
    __shared__ float sX[TOK_TILE * DC];   // 32 KB: x chunk, later reused for down tile
    __shared__ float sW[R_DIM * DC];      // 16 KB: gw / wu chunk, also stats scratch

    const int tid  = threadIdx.x;
    const int lane = tid & 31;
    const int wrp  = tid >> 5;
    const int mg   = wrp & 3;   // token group: tokens [mg*32, mg*32+32)
    const int ng   = wrp >> 2;  // n group: n-tiles [ng*4, ng*4+4)
    const int t0   = blockIdx.x * TOK_TILE;

    const float scaleV = scale[0];

    float acc[2][4][4];
    #pragma unroll
    for (int s = 0; s < 2; s++)
        #pragma unroll
        for (int nt = 0; nt < 4; nt++)
            #pragma unroll
            for (int i = 0; i < 4; i++) acc[s][nt][i] = 0.f;

    float sum8[8], sq8[8];
    #pragma unroll
    for (int i = 0; i < 8; i++) { sum8[i] = 0.f; sq8[i] = 0.f; }

    const float4* __restrict__ xg = reinterpret_cast<const float4*>(x) + (size_t)t0 * (D_DIM / 4);
    const float4* __restrict__ wg = reinterpret_cast<const float4*>(w_down);
    const float4* __restrict__ gg = reinterpret_cast<const float4*>(gamma);

    // ===================== Pass 1: stats + G = x @ (gamma*w_down)^T =====================
    for (int c = 0; c < NCHUNK; c++) {
        const int cb4 = c * (DC / 4);

        // stage x chunk [128 tok x 64 d], accumulate stats in regs
        #pragma unroll
        for (int i = 0; i < 8; i++) {
            int idx4 = i * 256 + tid;
            int t  = idx4 >> 4;
            int c4 = idx4 & 15;
            float4 v = xg[(size_t)t * (D_DIM / 4) + cb4 + c4];
            sum8[i] += v.x + v.y + v.z + v.w;
            sq8[i]  += v.x * v.x + v.y * v.y + v.z * v.z + v.w * v.w;
            int p = swz4(t, c4) * 4;
            sX[p] = v.x; sX[p + 1] = v.y; sX[p + 2] = v.z; sX[p + 3] = v.w;
        }
        // stage gw chunk [64 r x 64 d], fold gamma, round to tf32
        #pragma unroll
        for (int i = 0; i < 4; i++) {
            int idx4 = i * 256 + tid;
            int r  = idx4 >> 4;
            int c4 = idx4 & 15;
            float4 wv = wg[(size_t)r * (D_DIM / 4) + cb4 + c4];
            float4 gv = gg[cb4 + c4];
            int p = swz4(r, c4) * 4;
            sW[p]     = to_tf32(wv.x * gv.x);
            sW[p + 1] = to_tf32(wv.y * gv.y);
            sW[p + 2] = to_tf32(wv.z * gv.z);
            sW[p + 3] = to_tf32(wv.w * gv.w);
        }
        __syncthreads();

        #pragma unroll
        for (int ks = 0; ks < 8; ks++) {
            int kb = ks * 8 + (lane & 3);
            unsigned a[2][4];
            #pragma unroll
            for (int s = 0; s < 2; s++) {
                int r0 = mg * 32 + s * 16 + (lane >> 2);
                a[s][0] = __float_as_uint(sX[swzf(r0,     kb)]);
                a[s][1] = __float_as_uint(sX[swzf(r0 + 8, kb)]);
                a[s][2] = __float_as_uint(sX[swzf(r0,     kb + 4)]);
                a[s][3] = __float_as_uint(sX[swzf(r0 + 8, kb + 4)]);
            }
            #pragma unroll
            for (int nt = 0; nt < 4; nt++) {
                int n = (ng * 4 + nt) * 8 + (lane >> 2);
                unsigned b[2];
                b[0] = __float_as_uint(sW[swzf(n, kb)]);
                b[1] = __float_as_uint(sW[swzf(n, kb + 4)]);
                mma_tf32(acc[0][nt], a[0], b);
                mma_tf32(acc[1][nt], a[1], b);
            }
        }
        __syncthreads();
    }

    // ===================== stats finalize =====================
    // dump per-thread partials into sW (4096 floats = exactly sW)
    #pragma unroll
    for (int i = 0; i < 8; i++) {
        sW[i * 256 + tid]        = sum8[i];
        sW[2048 + i * 256 + tid] = sq8[i];
    }
    __syncthreads();

    float muT = 0.f, rsT = 0.f;
    if (tid < TOK_TILE) {
        int i    = tid >> 4;         // which i-slot holds this token
        int base = (tid & 15) * 16;  // which 16 threads hold it
        float s = 0.f, q = 0.f;
        #pragma unroll
        for (int j = 0; j < 16; j++) {
            s += sW[i * 256 + base + j];
            q += sW[2048 + i * 256 + base + j];
        }
        muT = s * (1.0f / (float)D_DIM);
        float var = q * (1.0f / (float)D_DIM) - muT * muT;
        rsT = rsqrtf(var + EPS);
    }
    __syncthreads();
    if (tid < TOK_TILE) { sW[tid] = muT; sW[TOK_TILE + tid] = rsT; }
    __syncthreads();

    // ===================== down = relu(rstd*(G - mu*C1) + C2 + b_down) -> sX =====================
    #pragma unroll
    for (int s = 0; s < 2; s++)
        #pragma unroll
        for (int nt = 0; nt < 4; nt++)
            #pragma unroll
            for (int i = 0; i < 4; i++) {
                int t = mg * 32 + s * 16 + (lane >> 2) + ((i >> 1) << 3);
                int r = (ng * 4 + nt) * 8 + 2 * (lane & 3) + (i & 1);
                float mu_t = sW[t];
                float rs_t = sW[TOK_TILE + t];
                float dv = rs_t * (acc[s][nt][i] - mu_t * g_C1[r]) + g_C2[r] + b_down[r];
                sX[swzf(t, r)] = fmaxf(dv, 0.f);
            }
    __syncthreads();

    // ===================== Pass 2: up = down @ w_up^T; out = x + scale*(up + b_up) =====================
    const float4* __restrict__ wug = reinterpret_cast<const float4*>(w_up);

    for (int c = 0; c < NCHUNK; c++) {
        // stage wu chunk: rows = local d in [0,64), cols = r in [0,64)
        #pragma unroll
        for (int i = 0; i < 4; i++) {
            int idx4 = i * 256 + tid;
            int dr = idx4 >> 4;
            int c4 = idx4 & 15;
            float4 wv = wug[(size_t)(c * DC + dr) * (R_DIM / 4) + c4];
            int p = swz4(dr, c4) * 4;
            sW[p]     = to_tf32(wv.x);
            sW[p + 1] = to_tf32(wv.y);
            sW[p + 2] = to_tf32(wv.z);
            sW[p + 3] = to_tf32(wv.w);
        }
        __syncthreads();

        float a2[2][4][4];
        #pragma unroll
        for (int s = 0; s < 2; s++)
            #pragma unroll
            for (int nt = 0; nt < 4; nt++)
                #pragma unroll
                for (int i = 0; i < 4; i++) a2[s][nt][i] = 0.f;

        #pragma unroll
        for (int ks = 0; ks < 8; ks++) {
            int kb = ks * 8 + (lane & 3);
            unsigned a[2][4];
            #pragma unroll
            for (int s = 0; s < 2; s++) {
                int r0 = mg * 32 + s * 16 + (lane >> 2);
                a[s][0] = __float_as_uint(sX[swzf(r0,     kb)]);
                a[s][1] = __float_as_uint(sX[swzf(r0 + 8, kb)]);
                a[s][2] = __float_as_uint(sX[swzf(r0,     kb + 4)]);
                a[s][3] = __float_as_uint(sX[swzf(r0 + 8, kb + 4)]);
            }
            #pragma unroll
            for (int nt = 0; nt < 4; nt++) {
                int n = (ng * 4 + nt) * 8 + (lane >> 2);
                unsigned b[2];
                b[0] = __float_as_uint(sW[swzf(n, kb)]);
                b[1] = __float_as_uint(sW[swzf(n, kb + 4)]);
                mma_tf32(a2[0][nt], a[0], b);
                mma_tf32(a2[1][nt], a[1], b);
            }
        }

        // epilogue: out = x + scale*(up + b_up)
        #pragma unroll
        for (int s = 0; s < 2; s++) {
            #pragma unroll
            for (int nt = 0; nt < 4; nt++) {
                int dl = (ng * 4 + nt) * 8 + 2 * (lane & 3);
                int d  = c * DC + dl;
                float2 bu = *reinterpret_cast<const float2*>(b_up + d);
                int trow = t0 + mg * 32 + s * 16 + (lane >> 2);

                float2 xv0 = *reinterpret_cast<const float2*>(x + (size_t)trow * D_DIM + d);
                float2 o0;
                o0.x = xv0.x + scaleV * (a2[s][nt][0] + bu.x);
                o0.y = xv0.y + scaleV * (a2[s][nt][1] + bu.y);
                *reinterpret_cast<float2*>(out + (size_t)trow * D_DIM + d) = o0;

                float2 xv8 = *reinterpret_cast<const float2*>(x + (size_t)(trow + 8) * D_DIM + d);
                float2 o8;
                o8.x = xv8.x + scaleV * (a2[s][nt][2] + bu.x);
                o8.y = xv8.y + scaleV * (a2[s][nt][3] + bu.y);
                *reinterpret_cast<float2*>(out + (size_t)(trow + 8) * D_DIM + d) = o8;
            }
        }
        __syncthreads();
    }
}

// ---------------- launch ----------------

extern "C" void kernel_launch(void* const* d_in, const int* in_sizes, int n_in,
                              void* d_out, int out_size) {
    const float* x       = (const float*)d_in[0];
    const float* gamma   = (const float*)d_in[1];
    const float* beta    = (const float*)d_in[2];
    const float* w_down  = (const float*)d_in[3];
    const float* b_down  = (const float*)d_in[4];
    const float* w_up    = (const float*)d_in[5];
    const float* b_up    = (const float*)d_in[6];
    const float* scale   = (const float*)d_in[7];
    float* out           = (float*)d_out;

    prep_c12<<<R_DIM, 256>>>(w_down, gamma, beta);
    adapter_main<<<N_TOK / TOK_TILE, 256>>>(x, gamma, w_down, b_down, w_up, b_up, scale, out);
}